// round 3
// baseline (speedup 1.0000x reference)
#include <cuda_runtime.h>
#include <cstdint>

// RobustTripletLoss — N=4096, D=512, C=128, TOPK=12
// K0: row norms | K1: symmetric fp32 GEMM (fma.rn.f32x2) -> 64MB dist scratch
// K2: per-row reduce (top-12, partitionable-threefry gumbel argmax, case logic)
// K3: deterministic final reduce -> out[0]=loss, out[1]=(float)correct
//
// RNG: JAX jax_threefry_partitionable=True (default since 0.4.36):
//   split(key)[i]     = full (x,y) of threefry2x32(key, (0, i))
//   random_bits u32[m]= x ^ y of threefry2x32(key, (hi32(m), lo32(m)))  [hi=0 here]
// gumbel argmax == argmax of (bits>>9) with first-index tie-break (monotone map).

namespace {

constexpr int NROW = 4096;
constexpr int DIM  = 512;
constexpr int NCLS = 128;
constexpr int KTOP = 12;

__device__ float g_dist[(size_t)NROW * NROW];
__device__ float g_sq[NROW];
__device__ float g_rowloss[NROW];
__device__ int   g_flags[NROW];

// ---------------- threefry2x32-20 (exact JAX semantics) ----------------
__host__ __device__ inline uint2 tf2x32(unsigned k0, unsigned k1,
                                        unsigned x0, unsigned x1) {
    unsigned ks2 = k0 ^ k1 ^ 0x1BD11BDAu;
    x0 += k0; x1 += k1;
#define TF_R(r) { x0 += x1; x1 = (x1 << (r)) | (x1 >> (32 - (r))); x1 ^= x0; }
    TF_R(13) TF_R(15) TF_R(26) TF_R(6)
    x0 += k1;  x1 += ks2 + 1u;
    TF_R(17) TF_R(29) TF_R(16) TF_R(24)
    x0 += ks2; x1 += k0 + 2u;
    TF_R(13) TF_R(15) TF_R(26) TF_R(6)
    x0 += k0;  x1 += k1 + 3u;
    TF_R(17) TF_R(29) TF_R(16) TF_R(24)
    x0 += k1;  x1 += ks2 + 4u;
    TF_R(13) TF_R(15) TF_R(26) TF_R(6)
    x0 += ks2; x1 += k0 + 5u;
#undef TF_R
    uint2 r; r.x = x0; r.y = x1; return r;
}

// partitionable random_bits for 32-bit draws, linear index m (< 2^32)
__device__ __forceinline__ unsigned rbits32(unsigned k0, unsigned k1, unsigned m) {
    uint2 e = tf2x32(k0, k1, 0u, m);
    return e.x ^ e.y;
}

// ---------------- packed f32x2 helpers ----------------
__device__ __forceinline__ unsigned long long pack2(float lo, float hi) {
    unsigned long long r;
    asm("mov.b64 %0, {%1, %2};" : "=l"(r) : "f"(lo), "f"(hi));
    return r;
}
__device__ __forceinline__ void unpack2(unsigned long long v, float& lo, float& hi) {
    asm("mov.b64 {%0, %1}, %2;" : "=f"(lo), "=f"(hi) : "l"(v));
}
__device__ __forceinline__ void fma2(unsigned long long& d,
                                     unsigned long long a, unsigned long long b) {
    asm("fma.rn.f32x2 %0, %1, %2, %0;" : "+l"(d) : "l"(a), "l"(b));
}

__device__ __forceinline__ float devInf() { return __int_as_float(0x7f800000); }

// ---------------- K0: row squared norms ----------------
__global__ void __launch_bounds__(256) k_sq(const float* __restrict__ X) {
    int row  = blockIdx.x * 8 + (threadIdx.x >> 5);
    int lane = threadIdx.x & 31;
    const float* p = X + (size_t)row * DIM;
    float s = 0.f;
#pragma unroll
    for (int k = lane; k < DIM; k += 32) { float v = p[k]; s = fmaf(v, v, s); }
#pragma unroll
    for (int o = 16; o > 0; o >>= 1) s += __shfl_xor_sync(0xffffffffu, s, o);
    if (lane == 0) g_sq[row] = s;
}

// ---------------- K1: symmetric GEMM + dist epilogue ----------------
__global__ void __launch_bounds__(256) k_gemm(const float* __restrict__ X) {
    const int bi = blockIdx.y, bj = blockIdx.x;
    if (bj < bi) return;

    __shared__ __align__(16) float As[16][128];
    __shared__ __align__(16) float Bs[16][128];

    const int tid = threadIdx.x;
    const int tx = tid & 15, ty = tid >> 4;
    const int rm = ty * 8, rn = tx * 8;
    const int lrow = tid >> 1;
    const int lcol = (tid & 1) * 8;

    const float* Ap = X + (size_t)(bi * 128 + lrow) * DIM + lcol;
    const float* Bp = X + (size_t)(bj * 128 + lrow) * DIM + lcol;

    unsigned long long acc[4][8];
#pragma unroll
    for (int a = 0; a < 4; a++)
#pragma unroll
        for (int b = 0; b < 8; b++) acc[a][b] = 0ull;

    for (int k0 = 0; k0 < DIM; k0 += 16) {
        float4 a0 = *(const float4*)(Ap + k0);
        float4 a1 = *(const float4*)(Ap + k0 + 4);
        float4 b0 = *(const float4*)(Bp + k0);
        float4 b1 = *(const float4*)(Bp + k0 + 4);
        __syncthreads();
        As[lcol + 0][lrow] = a0.x; As[lcol + 1][lrow] = a0.y;
        As[lcol + 2][lrow] = a0.z; As[lcol + 3][lrow] = a0.w;
        As[lcol + 4][lrow] = a1.x; As[lcol + 5][lrow] = a1.y;
        As[lcol + 6][lrow] = a1.z; As[lcol + 7][lrow] = a1.w;
        Bs[lcol + 0][lrow] = b0.x; Bs[lcol + 1][lrow] = b0.y;
        Bs[lcol + 2][lrow] = b0.z; Bs[lcol + 3][lrow] = b0.w;
        Bs[lcol + 4][lrow] = b1.x; Bs[lcol + 5][lrow] = b1.y;
        Bs[lcol + 6][lrow] = b1.z; Bs[lcol + 7][lrow] = b1.w;
        __syncthreads();
#pragma unroll
        for (int k = 0; k < 16; k++) {
            ulonglong2 A01 = *(const ulonglong2*)&As[k][rm];
            ulonglong2 A23 = *(const ulonglong2*)&As[k][rm + 4];
            float4 bb0 = *(const float4*)&Bs[k][rn];
            float4 bb1 = *(const float4*)&Bs[k][rn + 4];
            unsigned long long av[4] = {A01.x, A01.y, A23.x, A23.y};
            unsigned long long bp2[8];
            bp2[0] = pack2(bb0.x, bb0.x); bp2[1] = pack2(bb0.y, bb0.y);
            bp2[2] = pack2(bb0.z, bb0.z); bp2[3] = pack2(bb0.w, bb0.w);
            bp2[4] = pack2(bb1.x, bb1.x); bp2[5] = pack2(bb1.y, bb1.y);
            bp2[6] = pack2(bb1.z, bb1.z); bp2[7] = pack2(bb1.w, bb1.w);
#pragma unroll
            for (int a = 0; a < 4; a++)
#pragma unroll
                for (int b = 0; b < 8; b++) fma2(acc[a][b], av[a], bp2[b]);
        }
    }

    float sqm[8], sqn[8];
#pragma unroll
    for (int a = 0; a < 8; a++) sqm[a] = g_sq[bi * 128 + rm + a];
#pragma unroll
    for (int b = 0; b < 8; b++) sqn[b] = g_sq[bj * 128 + rn + b];

#pragma unroll
    for (int a = 0; a < 4; a++) {
#pragma unroll
        for (int b = 0; b < 8; b++) {
            float lo, hi; unpack2(acc[a][b], lo, hi);
            int gi0 = bi * 128 + rm + 2 * a;
            int gj  = bj * 128 + rn + b;
            float d0 = sqrtf(fmaxf(sqm[2 * a]     + sqn[b] - 2.f * lo, 1e-12f));
            float d1 = sqrtf(fmaxf(sqm[2 * a + 1] + sqn[b] - 2.f * hi, 1e-12f));
            g_dist[(size_t)gi0 * NROW + gj] = d0;
            g_dist[(size_t)(gi0 + 1) * NROW + gj] = d1;
            if (bi != bj) {
                g_dist[(size_t)gj * NROW + gi0] = d0;
                g_dist[(size_t)gj * NROW + gi0 + 1] = d1;
            }
        }
    }
}

// ---------------- block-wide u64 max reduce (broadcast result) ----------------
__device__ unsigned long long blockMax64(unsigned long long v,
                                         volatile unsigned long long* sh, int tid) {
#pragma unroll
    for (int o = 16; o > 0; o >>= 1) {
        unsigned long long o2 = __shfl_xor_sync(0xffffffffu, v, o);
        if (o2 > v) v = o2;
    }
    if ((tid & 31) == 0) sh[tid >> 5] = v;
    __syncthreads();
    if (tid == 0) {
        unsigned long long m = sh[0];
#pragma unroll
        for (int w = 1; w < 8; w++) { unsigned long long x = sh[w]; if (x > m) m = x; }
        sh[8] = m;
    }
    __syncthreads();
    return sh[8];
}

// ---------------- K2: per-row reduce ----------------
__global__ void __launch_bounds__(256) k_row(
    const float* __restrict__ pred, const int* __restrict__ targets,
    const float* __restrict__ prob, const float* __restrict__ thrp,
    unsigned kp0, unsigned kp1, unsigned q0, unsigned q1)
{
    const int i = blockIdx.x;
    const int tid = threadIdx.x;
    const float thr = *thrp;
    const int ti = targets[i];
    const float* grow = g_dist + (size_t)i * NROW;
    const float INF = devInf();

    __shared__ float sd[NROW];
    __shared__ unsigned long long sh[9];
    __shared__ int stop[KTOP];

    // single pass: build neg-masked dist + gumbel candidates (threefry only on mask)
    unsigned long long g1 = 0, g2 = 0;
    const unsigned mrow = (unsigned)i * (unsigned)NROW;
    for (int j = tid; j < NROW; j += 256) {
        float d = grow[j];
        bool same = (targets[j] == ti);
        sd[j] = same ? INF : d;
        if (same && j != i) {
            unsigned m = mrow + (unsigned)j;
            unsigned b1 = rbits32(kp0, kp1, m);
            unsigned long long s1 = (1ULL << 62) |
                ((unsigned long long)(b1 >> 9) << 13) | (unsigned)(NROW - 1 - j);
            if (s1 > g1) g1 = s1;
            if (prob[j] >= thr) {
                unsigned b2 = rbits32(q0, q1, m);
                unsigned long long s2 = (1ULL << 62) |
                    ((unsigned long long)(b2 >> 9) << 13) | (unsigned)(NROW - 1 - j);
                if (s2 > g2) g2 = s2;
            }
        }
    }
    __syncthreads();

    unsigned long long r1 = blockMax64(g1, sh, tid);
    unsigned long long r2 = blockMax64(g2, sh, tid);
    int ap_idx  = r1 ? (NROW - 1 - (int)(r1 & 0x1FFFu)) : 0;
    int new_pos = r2 ? (NROW - 1 - (int)(r2 & 0x1FFFu)) : ap_idx;

    // stable top-12 of neg distances: 12 destructive lexicographic argmin passes
    for (int t = 0; t < KTOP; t++) {
        unsigned long long best = 0;
        for (int j = tid; j < NROW; j += 256) {
            unsigned fb = __float_as_uint(sd[j]);  // all >= 0 or +inf
            unsigned long long sc = ~(((unsigned long long)fb << 13) | (unsigned)j);
            if (sc > best) best = sc;
        }
        unsigned long long r = blockMax64(best, sh, tid);
        int sel = (int)((~r) & 0x1FFFu);
        if (tid == 0) { stop[t] = sel; sd[sel] = INF; }
        __syncthreads();
    }
    int an_idx = stop[0];

    // argmax over prediction[an_idx] (first occurrence on ties)
    unsigned long long pm = 0;
    if (tid < NCLS) {
        float v = pred[(size_t)an_idx * NCLS + tid];
        unsigned b = __float_as_uint(v);
        unsigned ord = (b & 0x80000000u) ? ~b : (b | 0x80000000u);
        pm = ((unsigned long long)ord << 13) | (unsigned)(NCLS - 1 - tid);
    }
    unsigned long long rp = blockMax64(pm, sh, tid);
    int pargmax = NCLS - 1 - (int)(rp & 0x1FFFu);

    if (tid == 0) {
        float ap0 = grow[ap_idx];
        float an0 = grow[an_idx];
        bool pos_conf = prob[ap_idx] >= thr;
        bool neg_conf = prob[an_idx] >= thr;
        bool is_fn = (pargmax == ti);

        int rsel = KTOP - 1;
        for (int t = 1; t < KTOP; t++) {
            if (prob[stop[t]] >= thr) { rsel = t; break; }
        }
        float an_B   = grow[stop[rsel]];
        float ap_new = grow[new_pos];

        bool caseB   = pos_conf && !neg_conf && is_fn;
        bool swapc   = !pos_conf && (neg_conf || !is_fn);
        bool inverse = !pos_conf && !neg_conf && is_fn;
        float half = (ap0 + an0) * 0.5f;
        float ap = caseB ? half : (swapc ? ap_new : ap0);
        float an = caseB ? an_B : (swapc ? half  : an0);
        float rl = inverse ? fmaxf(an - ap + 0.3f, 0.f)
                           : fmaxf(ap - an + 0.3f, 0.f);
        bool conf = prob[i] >= thr;
        g_rowloss[i] = conf ? rl : 0.f;
        g_flags[i] = (conf ? 1 : 0) | ((conf && an >= ap) ? 2 : 0);
    }
}

// ---------------- K3: deterministic final reduce ----------------
__global__ void __launch_bounds__(256) k_final(float* out) {
    __shared__ float ss[256];
    __shared__ int sc[256], sk[256];
    int tid = threadIdx.x;
    float s = 0.f; int c = 0, k = 0;
    for (int r = tid; r < NROW; r += 256) {
        s += g_rowloss[r];
        int f = g_flags[r];
        c += f & 1;
        k += (f >> 1) & 1;
    }
    ss[tid] = s; sc[tid] = c; sk[tid] = k;
    __syncthreads();
    for (int o = 128; o > 0; o >>= 1) {
        if (tid < o) { ss[tid] += ss[tid + o]; sc[tid] += sc[tid + o]; sk[tid] += sk[tid + o]; }
        __syncthreads();
    }
    if (tid == 0) {
        int cnt = sc[0]; if (cnt < 1) cnt = 1;
        out[0] = ss[0] / (float)cnt;
        out[1] = (float)sk[0];
    }
}

}  // namespace

extern "C" void kernel_launch(void* const* d_in, const int* in_sizes, int n_in,
                              void* d_out, int out_size) {
    const float* X       = (const float*)d_in[0];
    const float* pred    = (const float*)d_in[1];
    const int*   targets = (const int*)d_in[2];
    // d_in[3] = true_targets (unused by reference)
    const float* prob    = (const float*)d_in[4];
    const float* thr     = (const float*)d_in[5];
    float* out = (float*)d_out;

    // JAX partitionable split: child key i = threefry2x32((0,42), (0, i)) full output
    uint2 kp  = tf2x32(0u, 42u, 0u, 0u);   // kp
    uint2 kp2 = tf2x32(0u, 42u, 0u, 1u);   // kp2

    k_sq<<<NROW / 8, 256>>>(X);
    dim3 g(NROW / 128, NROW / 128);
    k_gemm<<<g, 256>>>(X);
    k_row<<<NROW, 256>>>(pred, targets, prob, thr, kp.x, kp.y, kp2.x, kp2.y);
    k_final<<<1, 256>>>(out);
}